// round 4
// baseline (speedup 1.0000x reference)
#include <cuda_runtime.h>
#include <cuda_bf16.h>
#include <math.h>

// Problem constants
#define BB 256   // batch
#define TT 64    // encoder seq len
#define HH 1024  // hidden
#define GG 4096  // 4*H
#define VV 128   // vocab
#define LL 32    // decoder len

// GEMM tiling
#define BM 64
#define BN 128
#define BK 16
#define PADA 66   // As row stride in floats (bank-conflict-free STS, 8B aligned rows)

// ---------------- device state (no allocations allowed) ----------------
__device__ float d_hbuf[2][BB * HH];
__device__ float d_cbuf[BB * HH];
__device__ float d_encX[VV * GG];   // packed: [v][k*4+g] = emb[v]@W[:,g*1024+k] + b
__device__ float d_decX[VV * GG];
__device__ int   d_tok[BB];

// ---------------- helpers ----------------
__device__ __forceinline__ unsigned long long dup2(float x) {
    unsigned long long r;
    unsigned xi = __float_as_uint(x);
    asm("mov.b64 %0, {%1, %1};" : "=l"(r) : "r"(xi));
    return r;
}
__device__ __forceinline__ void fma2(unsigned long long& d, unsigned long long a,
                                     unsigned long long b) {
    asm("fma.rn.f32x2 %0, %1, %2, %0;" : "+l"(d) : "l"(a), "l"(b));
}
__device__ __forceinline__ float2 unpack2(unsigned long long v) {
    unsigned lo, hi;
    asm("mov.b64 {%0, %1}, %2;" : "=r"(lo), "=r"(hi) : "l"(v));
    return make_float2(__uint_as_float(lo), __uint_as_float(hi));
}
__device__ __forceinline__ float sigmoidf_(float x) {
    return 1.0f / (1.0f + __expf(-x));
}
__device__ __forceinline__ float tanhf_(float x) {
    float a = fabsf(x);
    float e = __expf(2.0f * a);
    float t = 1.0f - 2.0f / (e + 1.0f);
    return copysignf(t, x);
}

// ---------------- init ----------------
__global__ void init_kernel() {
    int n = BB * HH;
    for (int i = blockIdx.x * blockDim.x + threadIdx.x; i < n;
         i += gridDim.x * blockDim.x) {
        d_hbuf[0][i] = 0.0f;
        d_cbuf[i]    = 0.0f;
    }
    if (blockIdx.x == 0 && threadIdx.x < BB) d_tok[threadIdx.x] = VV - 1;  // delimiter
}

// ---------------- table: Xp[v][k*4+g] = emb[v]@W[:,g*1024+k] + b[g*1024+k] ----------------
// grid 128 CTAs x 256 threads. CTA owns 32 original columns; thread owns 1 col x 16 vocab rows.
__global__ __launch_bounds__(256, 1) void table_kernel(
    const float* __restrict__ emb, const float* __restrict__ W,
    const float* __restrict__ bias, int which) {
    float* Xp = which ? d_decX : d_encX;
    __shared__ __align__(16) float semb[32][VV];   // [r][v]
    int tid = threadIdx.x;
    int c = blockIdx.x * 32 + (tid & 31);          // original column 0..4095
    int vg = tid >> 5;                             // 0..7 -> 16 vocab rows

    float acc[16];
#pragma unroll
    for (int j = 0; j < 16; j++) acc[j] = 0.0f;

    for (int r0 = 0; r0 < HH; r0 += 32) {
#pragma unroll
        for (int j = 0; j < 4; j++) {
            int idx4 = tid + 256 * j;              // 0..1023 float4s
            int v  = idx4 >> 3;                    // 0..127
            int rq = idx4 & 7;                     // 0..7
            float4 t4 = *(const float4*)&emb[(size_t)v * HH + r0 + (rq << 2)];
            semb[(rq << 2) + 0][v] = t4.x;
            semb[(rq << 2) + 1][v] = t4.y;
            semb[(rq << 2) + 2][v] = t4.z;
            semb[(rq << 2) + 3][v] = t4.w;
        }
        __syncthreads();
#pragma unroll 8
        for (int r = 0; r < 32; r++) {
            float w = W[(size_t)(r0 + r) * GG + c];
            const float* sp = &semb[r][vg << 4];
#pragma unroll
            for (int j = 0; j < 16; j++) acc[j] += sp[j] * w;
        }
        __syncthreads();
    }
    int k = c & (HH - 1);
    int g = c >> 10;
    float bv = bias[c];
#pragma unroll
    for (int j = 0; j < 16; j++) {
        int v = (vg << 4) + j;
        Xp[(size_t)v * GG + (k << 2) + g] = acc[j] + bv;
    }
}

// ---------------- fused LSTM step: z = h@U + Xp[tok]; gates; masked state update ------------
// grid (32, 4), 256 threads. CTA tile: 64 rows x 128 packed cols (= 32 hidden units x 4 gates)
__global__ __launch_bounds__(256, 1) void lstm_step_kernel(
    const float* __restrict__ U, int xp_dec,
    const int* __restrict__ tokptr, int tokstride, int tok_mode, int parity) {
    const float* __restrict__ hin  = d_hbuf[parity];
    float* __restrict__ hout       = d_hbuf[parity ^ 1];
    const float* __restrict__ Xp   = xp_dec ? d_decX : d_encX;

    __shared__ __align__(16) float As[2][BK][PADA];
    __shared__ __align__(16) float Bs[2][BK][BN];
    __shared__ int stok[BM];

    int tid = threadIdx.x;
    int bm0 = blockIdx.y * BM;
    int bn0 = blockIdx.x * BN;     // packed col base (multiple of 128)
    int ku0 = bn0 >> 2;            // hidden-unit base

    // tokens for this row tile
    if (tid < BM) {
        if (tok_mode) stok[tid] = d_tok[bm0 + tid];
        else          stok[tid] = tokptr[(size_t)(bm0 + tid) * tokstride];
    }

    int tx = tid & 31;             // 32 col groups of 4 packed cols
    int ty = tid >> 5;             // 8 row groups of 8 rows

    // A staging: thread -> (row, k-quad)
    int a_row = tid >> 2;
    int a_kq  = tid & 3;
    const float* a_src = hin + (size_t)(bm0 + a_row) * HH + (a_kq << 2);

    unsigned long long acc[4][4];
#pragma unroll
    for (int i = 0; i < 4; i++)
#pragma unroll
        for (int j = 0; j < 4; j++) acc[i][j] = 0ull;

    float4 ga;
    float  gb[8];

    // prefetch tile 0
    {
        ga = *(const float4*)(a_src + 0);
#pragma unroll
        for (int j = 0; j < 8; j++) {
            int idx = tid + 256 * j;
            int k = idx >> 7, pc = idx & 127;
            int ku = pc >> 2, g = pc & 3;
            gb[j] = U[(size_t)(0 + k) * GG + g * 1024 + ku0 + ku];
        }
        As[0][(a_kq << 2) + 0][a_row] = ga.x;
        As[0][(a_kq << 2) + 1][a_row] = ga.y;
        As[0][(a_kq << 2) + 2][a_row] = ga.z;
        As[0][(a_kq << 2) + 3][a_row] = ga.w;
#pragma unroll
        for (int j = 0; j < 8; j++) {
            int idx = tid + 256 * j;
            Bs[0][idx >> 7][idx & 127] = gb[j];
        }
    }
    __syncthreads();

    const int NIT = HH / BK;  // 64
    for (int it = 0; it < NIT; it++) {
        if (it + 1 < NIT) {
            int k0 = (it + 1) * BK;
            ga = *(const float4*)(a_src + k0);
#pragma unroll
            for (int j = 0; j < 8; j++) {
                int idx = tid + 256 * j;
                int k = idx >> 7, pc = idx & 127;
                int ku = pc >> 2, g = pc & 3;
                gb[j] = U[(size_t)(k0 + k) * GG + g * 1024 + ku0 + ku];
            }
        }
        int buf = it & 1;
#pragma unroll
        for (int k = 0; k < BK; k++) {
            const unsigned long long* ap =
                reinterpret_cast<const unsigned long long*>(&As[buf][k][ty << 3]);
            unsigned long long a0 = ap[0], a1 = ap[1], a2 = ap[2], a3 = ap[3];
            float4 b4 = *reinterpret_cast<const float4*>(&Bs[buf][k][tx << 2]);
            unsigned long long b0 = dup2(b4.x), b1 = dup2(b4.y);
            unsigned long long b2 = dup2(b4.z), b3 = dup2(b4.w);
            fma2(acc[0][0], a0, b0); fma2(acc[0][1], a0, b1);
            fma2(acc[0][2], a0, b2); fma2(acc[0][3], a0, b3);
            fma2(acc[1][0], a1, b0); fma2(acc[1][1], a1, b1);
            fma2(acc[1][2], a1, b2); fma2(acc[1][3], a1, b3);
            fma2(acc[2][0], a2, b0); fma2(acc[2][1], a2, b1);
            fma2(acc[2][2], a2, b2); fma2(acc[2][3], a2, b3);
            fma2(acc[3][0], a3, b0); fma2(acc[3][1], a3, b1);
            fma2(acc[3][2], a3, b2); fma2(acc[3][3], a3, b3);
        }
        if (it + 1 < NIT) {
            int nb = (it + 1) & 1;
            As[nb][(a_kq << 2) + 0][a_row] = ga.x;
            As[nb][(a_kq << 2) + 1][a_row] = ga.y;
            As[nb][(a_kq << 2) + 2][a_row] = ga.z;
            As[nb][(a_kq << 2) + 3][a_row] = ga.w;
#pragma unroll
            for (int j = 0; j < 8; j++) {
                int idx = tid + 256 * j;
                Bs[nb][idx >> 7][idx & 127] = gb[j];
            }
        }
        __syncthreads();
    }

    // epilogue: gates + masked state update
    int pcg = bn0 + (tx << 2);   // packed col base for this thread
    int kg  = pcg >> 2;          // hidden unit index
#pragma unroll
    for (int rp = 0; rp < 4; rp++) {
        float2 zi2 = unpack2(acc[rp][0]);
        float2 zf2 = unpack2(acc[rp][1]);
        float2 zg2 = unpack2(acc[rp][2]);
        float2 zo2 = unpack2(acc[rp][3]);
#pragma unroll
        for (int hh = 0; hh < 2; hh++) {
            int row = (ty << 3) + (rp << 1) + hh;
            int b = bm0 + row;
            int tokb = stok[row];
            float4 xv = *(const float4*)&Xp[(size_t)tokb * GG + pcg];
            float zi = (hh ? zi2.y : zi2.x) + xv.x;
            float zf = (hh ? zf2.y : zf2.x) + xv.y;
            float zg = (hh ? zg2.y : zg2.x) + xv.z;
            float zo = (hh ? zo2.y : zo2.x) + xv.w;
            float ig = sigmoidf_(zi);
            float fg = sigmoidf_(zf);
            float gg = tanhf_(zg);
            float og = sigmoidf_(zo);
            size_t off = (size_t)b * HH + kg;
            float cold = d_cbuf[off];
            float c2 = fg * cold + ig * gg;
            float h2 = og * tanhf_(c2);
            if (tokb != 0) {
                d_cbuf[off] = c2;
                hout[off]   = h2;
            } else {
                hout[off] = hin[off];
            }
        }
    }
}

// ---------------- decoder output: logits->softmax->argmax, store y & tok -------------------
// grid 64 CTAs x 256 threads; CTA owns 4 batch rows.
__global__ __launch_bounds__(256, 2) void dec_out_kernel(
    const float* __restrict__ outW, const float* __restrict__ outb,
    float* __restrict__ dout, int out_size, int t, int parity) {
    const float* __restrict__ h = d_hbuf[parity];
    __shared__ __align__(16) float sh[4][HH];
    __shared__ float slog[4][VV];
    __shared__ float sexp[4][VV];
    __shared__ float ssum[4];
    __shared__ int   stk[4];

    int tid = threadIdx.x;
    int b0 = blockIdx.x * 4;

#pragma unroll
    for (int j = 0; j < 4; j++) {
        int idx4 = tid + 256 * j;          // 0..1023 float4s
        int row = idx4 >> 8;
        int c4 = idx4 & 255;
        *(float4*)&sh[row][c4 << 2] =
            *(const float4*)&h[(size_t)(b0 + row) * HH + (c4 << 2)];
    }
    __syncthreads();

    int v = tid & 127;
    int half = tid >> 7;
    float a0 = 0.0f, a1 = 0.0f;
    const float* s0 = sh[half * 2];
    const float* s1 = sh[half * 2 + 1];
#pragma unroll 8
    for (int k = 0; k < HH; k++) {
        float w = outW[(size_t)k * VV + v];
        a0 += s0[k] * w;
        a1 += s1[k] * w;
    }
    float bv = outb[v];
    slog[half * 2][v]     = a0 + bv;
    slog[half * 2 + 1][v] = a1 + bv;
    __syncthreads();

    if (tid < 128) {                       // warps 0..3, one row each
        int rw = tid >> 5;
        int lane = tid & 31;
        float m = -3.4e38f;
        int am = VV;
#pragma unroll
        for (int i = 0; i < 4; i++) {
            int vv = lane + (i << 5);
            float x = slog[rw][vv];
            if (x > m || (x == m && vv < am)) { m = x; am = vv; }
        }
#pragma unroll
        for (int off = 16; off; off >>= 1) {
            float om = __shfl_down_sync(0xffffffffu, m, off);
            int   oa = __shfl_down_sync(0xffffffffu, am, off);
            if (om > m || (om == m && oa < am)) { m = om; am = oa; }
        }
        m  = __shfl_sync(0xffffffffu, m, 0);
        am = __shfl_sync(0xffffffffu, am, 0);
        float s = 0.0f;
#pragma unroll
        for (int i = 0; i < 4; i++) {
            int vv = lane + (i << 5);
            float e = __expf(slog[rw][vv] - m);
            sexp[rw][vv] = e;
            s += e;
        }
#pragma unroll
        for (int off = 16; off; off >>= 1) s += __shfl_xor_sync(0xffffffffu, s, off);
        if (lane == 0) {
            ssum[rw] = s;
            stk[rw]  = am;
            d_tok[b0 + rw] = am;
        }
    }
    __syncthreads();

#pragma unroll
    for (int j = 0; j < 2; j++) {
        int idx = tid + 256 * j;           // 0..511
        int rw = idx >> 7;
        int vv = idx & 127;
        dout[((size_t)(b0 + rw) * LL + t) * VV + vv] = sexp[rw][vv] / ssum[rw];
    }
    if (out_size >= BB * LL * VV + LL * BB && tid < 4) {
        dout[(size_t)BB * LL * VV + (size_t)t * BB + (b0 + tid)] = (float)stk[tid];
    }
}

// ---------------- launcher ----------------
extern "C" void kernel_launch(void* const* d_in, const int* in_sizes, int n_in,
                              void* d_out, int out_size) {
    int idx = 0;
    const int* inputs = (const int*)d_in[idx++];
    if (idx < n_in && in_sizes[idx] == 1) idx++;  // skip max_len scalar if present
    const float* enc_emb = (const float*)d_in[idx++];
    const float* enc_W   = (const float*)d_in[idx++];
    const float* enc_U   = (const float*)d_in[idx++];
    const float* enc_b   = (const float*)d_in[idx++];
    const float* dec_emb = (const float*)d_in[idx++];
    const float* dec_W   = (const float*)d_in[idx++];
    const float* dec_U   = (const float*)d_in[idx++];
    const float* dec_b   = (const float*)d_in[idx++];
    const float* out_W   = (const float*)d_in[idx++];
    const float* out_b   = (const float*)d_in[idx++];
    float* dout = (float*)d_out;

    init_kernel<<<256, 256>>>();
    table_kernel<<<128, 256>>>(enc_emb, enc_W, enc_b, 0);
    table_kernel<<<128, 256>>>(dec_emb, dec_W, dec_b, 1);

    dim3 grid(GG / BN, BB / BM);  // (32, 4)
    int par = 0;
    for (int t = 0; t < TT; t++) {
        lstm_step_kernel<<<grid, 256>>>(enc_U, 0, inputs + t, TT, 0, par);
        par ^= 1;
    }
    for (int s = 0; s < LL; s++) {
        lstm_step_kernel<<<grid, 256>>>(dec_U, 1, (const int*)0, 1, 1, par);
        par ^= 1;
        dec_out_kernel<<<64, 256>>>(out_W, out_b, dout, out_size, s, par);
    }
}

// round 5
// speedup vs baseline: 1.0010x; 1.0010x over previous
#include <cuda_runtime.h>
#include <cuda_bf16.h>
#include <math.h>

// Problem constants
#define BB 256   // batch
#define TT 64    // encoder seq len
#define HH 1024  // hidden
#define GG 4096  // 4*H
#define VV 128   // vocab
#define LL 32    // decoder len

// GEMM tiling
#define BM 64
#define BN 128
#define BK 16
#define PADA 66   // As row stride in floats (bank-conflict-free STS, 8B aligned rows)

// ---------------- device state (no allocations allowed) ----------------
__device__ float d_hbuf[2][BB * HH];
__device__ float d_cbuf[BB * HH];
__device__ float d_encX[VV * GG];   // packed: [v][k*4+g] = emb[v]@W[:,g*1024+k] + b
__device__ float d_decX[VV * GG];
__device__ int   d_tok[BB];

// ---------------- helpers ----------------
__device__ __forceinline__ unsigned long long dup2(float x) {
    unsigned long long r;
    unsigned xi = __float_as_uint(x);
    asm("mov.b64 %0, {%1, %1};" : "=l"(r) : "r"(xi));
    return r;
}
__device__ __forceinline__ void fma2(unsigned long long& d, unsigned long long a,
                                     unsigned long long b) {
    asm("fma.rn.f32x2 %0, %1, %2, %0;" : "+l"(d) : "l"(a), "l"(b));
}
__device__ __forceinline__ float2 unpack2(unsigned long long v) {
    unsigned lo, hi;
    asm("mov.b64 {%0, %1}, %2;" : "=r"(lo), "=r"(hi) : "l"(v));
    return make_float2(__uint_as_float(lo), __uint_as_float(hi));
}
__device__ __forceinline__ float sigmoidf_(float x) {
    return 1.0f / (1.0f + __expf(-x));
}
__device__ __forceinline__ float tanhf_(float x) {
    float a = fabsf(x);
    float e = __expf(2.0f * a);
    float t = 1.0f - 2.0f / (e + 1.0f);
    return copysignf(t, x);
}

// ---------------- init ----------------
__global__ void init_kernel() {
    int n = BB * HH;
    for (int i = blockIdx.x * blockDim.x + threadIdx.x; i < n;
         i += gridDim.x * blockDim.x) {
        d_hbuf[0][i] = 0.0f;
        d_cbuf[i]    = 0.0f;
    }
    if (blockIdx.x == 0 && threadIdx.x < BB) d_tok[threadIdx.x] = VV - 1;  // delimiter
}

// ---------------- table: Xp[v][k*4+g] = emb[v]@W[:,g*1024+k] + b[g*1024+k] ----------------
// grid 128 CTAs x 256 threads. CTA owns 32 original columns; thread owns 1 col x 16 vocab rows.
__global__ __launch_bounds__(256, 1) void table_kernel(
    const float* __restrict__ emb, const float* __restrict__ W,
    const float* __restrict__ bias, int which) {
    float* Xp = which ? d_decX : d_encX;
    __shared__ __align__(16) float semb[32][VV];   // [r][v]
    int tid = threadIdx.x;
    int c = blockIdx.x * 32 + (tid & 31);          // original column 0..4095
    int vg = tid >> 5;                             // 0..7 -> 16 vocab rows

    float acc[16];
#pragma unroll
    for (int j = 0; j < 16; j++) acc[j] = 0.0f;

    for (int r0 = 0; r0 < HH; r0 += 32) {
#pragma unroll
        for (int j = 0; j < 4; j++) {
            int idx4 = tid + 256 * j;              // 0..1023 float4s
            int v  = idx4 >> 3;                    // 0..127
            int rq = idx4 & 7;                     // 0..7
            float4 t4 = *(const float4*)&emb[(size_t)v * HH + r0 + (rq << 2)];
            semb[(rq << 2) + 0][v] = t4.x;
            semb[(rq << 2) + 1][v] = t4.y;
            semb[(rq << 2) + 2][v] = t4.z;
            semb[(rq << 2) + 3][v] = t4.w;
        }
        __syncthreads();
#pragma unroll 8
        for (int r = 0; r < 32; r++) {
            float w = W[(size_t)(r0 + r) * GG + c];
            const float* sp = &semb[r][vg << 4];
#pragma unroll
            for (int j = 0; j < 16; j++) acc[j] += sp[j] * w;
        }
        __syncthreads();
    }
    int k = c & (HH - 1);
    int g = c >> 10;
    float bv = bias[c];
#pragma unroll
    for (int j = 0; j < 16; j++) {
        int v = (vg << 4) + j;
        Xp[(size_t)v * GG + (k << 2) + g] = acc[j] + bv;
    }
}

// ---------------- fused LSTM step: z = h@U + Xp[tok]; gates; masked state update ------------
// grid (32, 4), 256 threads. CTA tile: 64 rows x 128 packed cols (= 32 hidden units x 4 gates)
__global__ __launch_bounds__(256, 1) void lstm_step_kernel(
    const float* __restrict__ U, int xp_dec,
    const int* __restrict__ tokptr, int tokstride, int tok_mode, int parity) {
    const float* __restrict__ hin  = d_hbuf[parity];
    float* __restrict__ hout       = d_hbuf[parity ^ 1];
    const float* __restrict__ Xp   = xp_dec ? d_decX : d_encX;

    __shared__ __align__(16) float As[2][BK][PADA];
    __shared__ __align__(16) float Bs[2][BK][BN];
    __shared__ int stok[BM];

    int tid = threadIdx.x;
    int bm0 = blockIdx.y * BM;
    int bn0 = blockIdx.x * BN;     // packed col base (multiple of 128)
    int ku0 = bn0 >> 2;            // hidden-unit base

    // tokens for this row tile
    if (tid < BM) {
        if (tok_mode) stok[tid] = d_tok[bm0 + tid];
        else          stok[tid] = tokptr[(size_t)(bm0 + tid) * tokstride];
    }

    int tx = tid & 31;             // 32 col groups of 4 packed cols
    int ty = tid >> 5;             // 8 row groups of 8 rows

    // A staging: thread -> (row, k-quad)
    int a_row = tid >> 2;
    int a_kq  = tid & 3;
    const float* a_src = hin + (size_t)(bm0 + a_row) * HH + (a_kq << 2);

    unsigned long long acc[4][4];
#pragma unroll
    for (int i = 0; i < 4; i++)
#pragma unroll
        for (int j = 0; j < 4; j++) acc[i][j] = 0ull;

    float4 ga;
    float  gb[8];

    // prefetch tile 0
    {
        ga = *(const float4*)(a_src + 0);
#pragma unroll
        for (int j = 0; j < 8; j++) {
            int idx = tid + 256 * j;
            int k = idx >> 7, pc = idx & 127;
            int ku = pc >> 2, g = pc & 3;
            gb[j] = U[(size_t)(0 + k) * GG + g * 1024 + ku0 + ku];
        }
        As[0][(a_kq << 2) + 0][a_row] = ga.x;
        As[0][(a_kq << 2) + 1][a_row] = ga.y;
        As[0][(a_kq << 2) + 2][a_row] = ga.z;
        As[0][(a_kq << 2) + 3][a_row] = ga.w;
#pragma unroll
        for (int j = 0; j < 8; j++) {
            int idx = tid + 256 * j;
            Bs[0][idx >> 7][idx & 127] = gb[j];
        }
    }
    __syncthreads();

    const int NIT = HH / BK;  // 64
    for (int it = 0; it < NIT; it++) {
        if (it + 1 < NIT) {
            int k0 = (it + 1) * BK;
            ga = *(const float4*)(a_src + k0);
#pragma unroll
            for (int j = 0; j < 8; j++) {
                int idx = tid + 256 * j;
                int k = idx >> 7, pc = idx & 127;
                int ku = pc >> 2, g = pc & 3;
                gb[j] = U[(size_t)(k0 + k) * GG + g * 1024 + ku0 + ku];
            }
        }
        int buf = it & 1;
#pragma unroll
        for (int k = 0; k < BK; k++) {
            const unsigned long long* ap =
                reinterpret_cast<const unsigned long long*>(&As[buf][k][ty << 3]);
            unsigned long long a0 = ap[0], a1 = ap[1], a2 = ap[2], a3 = ap[3];
            float4 b4 = *reinterpret_cast<const float4*>(&Bs[buf][k][tx << 2]);
            unsigned long long b0 = dup2(b4.x), b1 = dup2(b4.y);
            unsigned long long b2 = dup2(b4.z), b3 = dup2(b4.w);
            fma2(acc[0][0], a0, b0); fma2(acc[0][1], a0, b1);
            fma2(acc[0][2], a0, b2); fma2(acc[0][3], a0, b3);
            fma2(acc[1][0], a1, b0); fma2(acc[1][1], a1, b1);
            fma2(acc[1][2], a1, b2); fma2(acc[1][3], a1, b3);
            fma2(acc[2][0], a2, b0); fma2(acc[2][1], a2, b1);
            fma2(acc[2][2], a2, b2); fma2(acc[2][3], a2, b3);
            fma2(acc[3][0], a3, b0); fma2(acc[3][1], a3, b1);
            fma2(acc[3][2], a3, b2); fma2(acc[3][3], a3, b3);
        }
        if (it + 1 < NIT) {
            int nb = (it + 1) & 1;
            As[nb][(a_kq << 2) + 0][a_row] = ga.x;
            As[nb][(a_kq << 2) + 1][a_row] = ga.y;
            As[nb][(a_kq << 2) + 2][a_row] = ga.z;
            As[nb][(a_kq << 2) + 3][a_row] = ga.w;
#pragma unroll
            for (int j = 0; j < 8; j++) {
                int idx = tid + 256 * j;
                Bs[nb][idx >> 7][idx & 127] = gb[j];
            }
        }
        __syncthreads();
    }

    // epilogue: gates + masked state update
    int pcg = bn0 + (tx << 2);   // packed col base for this thread
    int kg  = pcg >> 2;          // hidden unit index
#pragma unroll
    for (int rp = 0; rp < 4; rp++) {
        float2 zi2 = unpack2(acc[rp][0]);
        float2 zf2 = unpack2(acc[rp][1]);
        float2 zg2 = unpack2(acc[rp][2]);
        float2 zo2 = unpack2(acc[rp][3]);
#pragma unroll
        for (int hh = 0; hh < 2; hh++) {
            int row = (ty << 3) + (rp << 1) + hh;
            int b = bm0 + row;
            int tokb = stok[row];
            float4 xv = *(const float4*)&Xp[(size_t)tokb * GG + pcg];
            float zi = (hh ? zi2.y : zi2.x) + xv.x;
            float zf = (hh ? zf2.y : zf2.x) + xv.y;
            float zg = (hh ? zg2.y : zg2.x) + xv.z;
            float zo = (hh ? zo2.y : zo2.x) + xv.w;
            float ig = sigmoidf_(zi);
            float fg = sigmoidf_(zf);
            float gg = tanhf_(zg);
            float og = sigmoidf_(zo);
            size_t off = (size_t)b * HH + kg;
            float cold = d_cbuf[off];
            float c2 = fg * cold + ig * gg;
            float h2 = og * tanhf_(c2);
            if (tokb != 0) {
                d_cbuf[off] = c2;
                hout[off]   = h2;
            } else {
                hout[off] = hin[off];
            }
        }
    }
}

// ---------------- decoder output: logits->softmax->argmax, store y & tok -------------------
// grid 64 CTAs x 256 threads; CTA owns 4 batch rows.
__global__ __launch_bounds__(256, 2) void dec_out_kernel(
    const float* __restrict__ outW, const float* __restrict__ outb,
    float* __restrict__ dout, int out_size, int t, int parity) {
    const float* __restrict__ h = d_hbuf[parity];
    __shared__ __align__(16) float sh[4][HH];
    __shared__ float slog[4][VV];
    __shared__ float sexp[4][VV];
    __shared__ float ssum[4];
    __shared__ int   stk[4];

    int tid = threadIdx.x;
    int b0 = blockIdx.x * 4;

#pragma unroll
    for (int j = 0; j < 4; j++) {
        int idx4 = tid + 256 * j;          // 0..1023 float4s
        int row = idx4 >> 8;
        int c4 = idx4 & 255;
        *(float4*)&sh[row][c4 << 2] =
            *(const float4*)&h[(size_t)(b0 + row) * HH + (c4 << 2)];
    }
    __syncthreads();

    int v = tid & 127;
    int half = tid >> 7;
    float a0 = 0.0f, a1 = 0.0f;
    const float* s0 = sh[half * 2];
    const float* s1 = sh[half * 2 + 1];
#pragma unroll 8
    for (int k = 0; k < HH; k++) {
        float w = outW[(size_t)k * VV + v];
        a0 += s0[k] * w;
        a1 += s1[k] * w;
    }
    float bv = outb[v];
    slog[half * 2][v]     = a0 + bv;
    slog[half * 2 + 1][v] = a1 + bv;
    __syncthreads();

    if (tid < 128) {                       // warps 0..3, one row each
        int rw = tid >> 5;
        int lane = tid & 31;
        float m = -3.4e38f;
        int am = VV;
#pragma unroll
        for (int i = 0; i < 4; i++) {
            int vv = lane + (i << 5);
            float x = slog[rw][vv];
            if (x > m || (x == m && vv < am)) { m = x; am = vv; }
        }
#pragma unroll
        for (int off = 16; off; off >>= 1) {
            float om = __shfl_down_sync(0xffffffffu, m, off);
            int   oa = __shfl_down_sync(0xffffffffu, am, off);
            if (om > m || (om == m && oa < am)) { m = om; am = oa; }
        }
        m  = __shfl_sync(0xffffffffu, m, 0);
        am = __shfl_sync(0xffffffffu, am, 0);
        float s = 0.0f;
#pragma unroll
        for (int i = 0; i < 4; i++) {
            int vv = lane + (i << 5);
            float e = __expf(slog[rw][vv] - m);
            sexp[rw][vv] = e;
            s += e;
        }
#pragma unroll
        for (int off = 16; off; off >>= 1) s += __shfl_xor_sync(0xffffffffu, s, off);
        if (lane == 0) {
            ssum[rw] = s;
            stk[rw]  = am;
            d_tok[b0 + rw] = am;
        }
    }
    __syncthreads();

#pragma unroll
    for (int j = 0; j < 2; j++) {
        int idx = tid + 256 * j;           // 0..511
        int rw = idx >> 7;
        int vv = idx & 127;
        dout[((size_t)(b0 + rw) * LL + t) * VV + vv] = sexp[rw][vv] / ssum[rw];
    }
    if (out_size >= BB * LL * VV + LL * BB && tid < 4) {
        dout[(size_t)BB * LL * VV + (size_t)t * BB + (b0 + tid)] = (float)stk[tid];
    }
}

// ---------------- launcher ----------------
extern "C" void kernel_launch(void* const* d_in, const int* in_sizes, int n_in,
                              void* d_out, int out_size) {
    int idx = 0;
    const int* inputs = (const int*)d_in[idx++];
    if (idx < n_in && in_sizes[idx] == 1) idx++;  // skip max_len scalar if present
    const float* enc_emb = (const float*)d_in[idx++];
    const float* enc_W   = (const float*)d_in[idx++];
    const float* enc_U   = (const float*)d_in[idx++];
    const float* enc_b   = (const float*)d_in[idx++];
    const float* dec_emb = (const float*)d_in[idx++];
    const float* dec_W   = (const float*)d_in[idx++];
    const float* dec_U   = (const float*)d_in[idx++];
    const float* dec_b   = (const float*)d_in[idx++];
    const float* out_W   = (const float*)d_in[idx++];
    const float* out_b   = (const float*)d_in[idx++];
    float* dout = (float*)d_out;

    init_kernel<<<256, 256>>>();
    table_kernel<<<128, 256>>>(enc_emb, enc_W, enc_b, 0);
    table_kernel<<<128, 256>>>(dec_emb, dec_W, dec_b, 1);

    dim3 grid(GG / BN, BB / BM);  // (32, 4)
    int par = 0;
    for (int t = 0; t < TT; t++) {
        lstm_step_kernel<<<grid, 256>>>(enc_U, 0, inputs + t, TT, 0, par);
        par ^= 1;
    }
    for (int s = 0; s < LL; s++) {
        lstm_step_kernel<<<grid, 256>>>(dec_U, 1, (const int*)0, 1, 1, par);
        par ^= 1;
        dec_out_kernel<<<64, 256>>>(out_W, out_b, dout, out_size, s, par);
    }
}

// round 6
// speedup vs baseline: 1.0105x; 1.0095x over previous
#include <cuda_runtime.h>
#include <cuda_bf16.h>
#include <math.h>

// Problem constants
#define BB 256   // batch
#define TT 64    // encoder seq len
#define HH 1024  // hidden
#define GG 4096  // 4*H
#define VV 128   // vocab
#define LL 32    // decoder len

// GEMM tiling
#define BM 64
#define BN 128
#define BK 16
#define PADA 66   // As row stride in floats (bank-conflict-free STS, 8B aligned rows)

// ---------------- device state (no allocations allowed) ----------------
__device__ float d_hbuf[2][BB * HH];
__device__ float d_cbuf[BB * HH];
__device__ float d_encX[VV * GG];   // packed: [v][k*4+g] = emb[v]@W[:,g*1024+k] + b
__device__ float d_decX[VV * GG];
__device__ int   d_tok[BB];

// ---------------- helpers ----------------
__device__ __forceinline__ unsigned long long dup2(float x) {
    unsigned long long r;
    unsigned xi = __float_as_uint(x);
    asm("mov.b64 %0, {%1, %1};" : "=l"(r) : "r"(xi));
    return r;
}
__device__ __forceinline__ void fma2(unsigned long long& d, unsigned long long a,
                                     unsigned long long b) {
    asm("fma.rn.f32x2 %0, %1, %2, %0;" : "+l"(d) : "l"(a), "l"(b));
}
__device__ __forceinline__ float2 unpack2(unsigned long long v) {
    unsigned lo, hi;
    asm("mov.b64 {%0, %1}, %2;" : "=r"(lo), "=r"(hi) : "l"(v));
    return make_float2(__uint_as_float(lo), __uint_as_float(hi));
}
__device__ __forceinline__ float sigmoidf_(float x) {
    return 1.0f / (1.0f + __expf(-x));
}
__device__ __forceinline__ float tanhf_(float x) {
    float a = fabsf(x);
    float e = __expf(2.0f * a);
    float t = 1.0f - 2.0f / (e + 1.0f);
    return copysignf(t, x);
}

// ---------------- init ----------------
__global__ void init_kernel() {
    int n = BB * HH;
    for (int i = blockIdx.x * blockDim.x + threadIdx.x; i < n;
         i += gridDim.x * blockDim.x) {
        d_hbuf[0][i] = 0.0f;
        d_cbuf[i]    = 0.0f;
    }
    if (blockIdx.x == 0 && threadIdx.x < BB) d_tok[threadIdx.x] = VV - 1;  // delimiter
}

// ---------------- table: Xp[v][k*4+g] = emb[v]@W[:,g*1024+k] + b[g*1024+k] ----------------
// grid 128 CTAs x 256 threads. CTA owns 32 original columns; thread owns 1 col x 16 vocab rows.
__global__ __launch_bounds__(256, 1) void table_kernel(
    const float* __restrict__ emb, const float* __restrict__ W,
    const float* __restrict__ bias, int which) {
    float* Xp = which ? d_decX : d_encX;
    __shared__ __align__(16) float semb[32][VV];   // [r][v]
    int tid = threadIdx.x;
    int c = blockIdx.x * 32 + (tid & 31);          // original column 0..4095
    int vg = tid >> 5;                             // 0..7 -> 16 vocab rows

    float acc[16];
#pragma unroll
    for (int j = 0; j < 16; j++) acc[j] = 0.0f;

    for (int r0 = 0; r0 < HH; r0 += 32) {
#pragma unroll
        for (int j = 0; j < 4; j++) {
            int idx4 = tid + 256 * j;              // 0..1023 float4s
            int v  = idx4 >> 3;                    // 0..127
            int rq = idx4 & 7;                     // 0..7
            float4 t4 = *(const float4*)&emb[(size_t)v * HH + r0 + (rq << 2)];
            semb[(rq << 2) + 0][v] = t4.x;
            semb[(rq << 2) + 1][v] = t4.y;
            semb[(rq << 2) + 2][v] = t4.z;
            semb[(rq << 2) + 3][v] = t4.w;
        }
        __syncthreads();
#pragma unroll 8
        for (int r = 0; r < 32; r++) {
            float w = W[(size_t)(r0 + r) * GG + c];
            const float* sp = &semb[r][vg << 4];
#pragma unroll
            for (int j = 0; j < 16; j++) acc[j] += sp[j] * w;
        }
        __syncthreads();
    }
    int k = c & (HH - 1);
    int g = c >> 10;
    float bv = bias[c];
#pragma unroll
    for (int j = 0; j < 16; j++) {
        int v = (vg << 4) + j;
        Xp[(size_t)v * GG + (k << 2) + g] = acc[j] + bv;
    }
}

// ---------------- fused LSTM step: z = h@U + Xp[tok]; gates; masked state update ------------
// grid (32, 4), 256 threads. CTA tile: 64 rows x 128 packed cols (= 32 hidden units x 4 gates)
__global__ __launch_bounds__(256, 1) void lstm_step_kernel(
    const float* __restrict__ U, int xp_dec,
    const int* __restrict__ tokptr, int tokstride, int tok_mode, int parity) {
    const float* __restrict__ hin  = d_hbuf[parity];
    float* __restrict__ hout       = d_hbuf[parity ^ 1];
    const float* __restrict__ Xp   = xp_dec ? d_decX : d_encX;

    __shared__ __align__(16) float As[2][BK][PADA];
    __shared__ __align__(16) float Bs[2][BK][BN];
    __shared__ int stok[BM];

    int tid = threadIdx.x;
    int bm0 = blockIdx.y * BM;
    int bn0 = blockIdx.x * BN;     // packed col base (multiple of 128)
    int ku0 = bn0 >> 2;            // hidden-unit base

    // tokens for this row tile
    if (tid < BM) {
        if (tok_mode) stok[tid] = d_tok[bm0 + tid];
        else          stok[tid] = tokptr[(size_t)(bm0 + tid) * tokstride];
    }

    int tx = tid & 31;             // 32 col groups of 4 packed cols
    int ty = tid >> 5;             // 8 row groups of 8 rows

    // A staging: thread -> (row, k-quad)
    int a_row = tid >> 2;
    int a_kq  = tid & 3;
    const float* a_src = hin + (size_t)(bm0 + a_row) * HH + (a_kq << 2);

    unsigned long long acc[4][4];
#pragma unroll
    for (int i = 0; i < 4; i++)
#pragma unroll
        for (int j = 0; j < 4; j++) acc[i][j] = 0ull;

    float4 ga;
    float  gb[8];

    // prefetch tile 0
    {
        ga = *(const float4*)(a_src + 0);
#pragma unroll
        for (int j = 0; j < 8; j++) {
            int idx = tid + 256 * j;
            int k = idx >> 7, pc = idx & 127;
            int ku = pc >> 2, g = pc & 3;
            gb[j] = U[(size_t)(0 + k) * GG + g * 1024 + ku0 + ku];
        }
        As[0][(a_kq << 2) + 0][a_row] = ga.x;
        As[0][(a_kq << 2) + 1][a_row] = ga.y;
        As[0][(a_kq << 2) + 2][a_row] = ga.z;
        As[0][(a_kq << 2) + 3][a_row] = ga.w;
#pragma unroll
        for (int j = 0; j < 8; j++) {
            int idx = tid + 256 * j;
            Bs[0][idx >> 7][idx & 127] = gb[j];
        }
    }
    __syncthreads();

    const int NIT = HH / BK;  // 64
    for (int it = 0; it < NIT; it++) {
        if (it + 1 < NIT) {
            int k0 = (it + 1) * BK;
            ga = *(const float4*)(a_src + k0);
#pragma unroll
            for (int j = 0; j < 8; j++) {
                int idx = tid + 256 * j;
                int k = idx >> 7, pc = idx & 127;
                int ku = pc >> 2, g = pc & 3;
                gb[j] = U[(size_t)(k0 + k) * GG + g * 1024 + ku0 + ku];
            }
        }
        int buf = it & 1;
#pragma unroll
        for (int k = 0; k < BK; k++) {
            const unsigned long long* ap =
                reinterpret_cast<const unsigned long long*>(&As[buf][k][ty << 3]);
            unsigned long long a0 = ap[0], a1 = ap[1], a2 = ap[2], a3 = ap[3];
            float4 b4 = *reinterpret_cast<const float4*>(&Bs[buf][k][tx << 2]);
            unsigned long long b0 = dup2(b4.x), b1 = dup2(b4.y);
            unsigned long long b2 = dup2(b4.z), b3 = dup2(b4.w);
            fma2(acc[0][0], a0, b0); fma2(acc[0][1], a0, b1);
            fma2(acc[0][2], a0, b2); fma2(acc[0][3], a0, b3);
            fma2(acc[1][0], a1, b0); fma2(acc[1][1], a1, b1);
            fma2(acc[1][2], a1, b2); fma2(acc[1][3], a1, b3);
            fma2(acc[2][0], a2, b0); fma2(acc[2][1], a2, b1);
            fma2(acc[2][2], a2, b2); fma2(acc[2][3], a2, b3);
            fma2(acc[3][0], a3, b0); fma2(acc[3][1], a3, b1);
            fma2(acc[3][2], a3, b2); fma2(acc[3][3], a3, b3);
        }
        if (it + 1 < NIT) {
            int nb = (it + 1) & 1;
            As[nb][(a_kq << 2) + 0][a_row] = ga.x;
            As[nb][(a_kq << 2) + 1][a_row] = ga.y;
            As[nb][(a_kq << 2) + 2][a_row] = ga.z;
            As[nb][(a_kq << 2) + 3][a_row] = ga.w;
#pragma unroll
            for (int j = 0; j < 8; j++) {
                int idx = tid + 256 * j;
                Bs[nb][idx >> 7][idx & 127] = gb[j];
            }
        }
        __syncthreads();
    }

    // epilogue: gates + masked state update
    int pcg = bn0 + (tx << 2);   // packed col base for this thread
    int kg  = pcg >> 2;          // hidden unit index
#pragma unroll
    for (int rp = 0; rp < 4; rp++) {
        float2 zi2 = unpack2(acc[rp][0]);
        float2 zf2 = unpack2(acc[rp][1]);
        float2 zg2 = unpack2(acc[rp][2]);
        float2 zo2 = unpack2(acc[rp][3]);
#pragma unroll
        for (int hh = 0; hh < 2; hh++) {
            int row = (ty << 3) + (rp << 1) + hh;
            int b = bm0 + row;
            int tokb = stok[row];
            float4 xv = *(const float4*)&Xp[(size_t)tokb * GG + pcg];
            float zi = (hh ? zi2.y : zi2.x) + xv.x;
            float zf = (hh ? zf2.y : zf2.x) + xv.y;
            float zg = (hh ? zg2.y : zg2.x) + xv.z;
            float zo = (hh ? zo2.y : zo2.x) + xv.w;
            float ig = sigmoidf_(zi);
            float fg = sigmoidf_(zf);
            float gg = tanhf_(zg);
            float og = sigmoidf_(zo);
            size_t off = (size_t)b * HH + kg;
            float cold = d_cbuf[off];
            float c2 = fg * cold + ig * gg;
            float h2 = og * tanhf_(c2);
            if (tokb != 0) {
                d_cbuf[off] = c2;
                hout[off]   = h2;
            } else {
                hout[off] = hin[off];
            }
        }
    }
}

// ---------------- decoder output: logits->softmax->argmax, store y & tok -------------------
// grid 64 CTAs x 256 threads; CTA owns 4 batch rows.
__global__ __launch_bounds__(256, 2) void dec_out_kernel(
    const float* __restrict__ outW, const float* __restrict__ outb,
    float* __restrict__ dout, int out_size, int t, int parity) {
    const float* __restrict__ h = d_hbuf[parity];
    __shared__ __align__(16) float sh[4][HH];
    __shared__ float slog[4][VV];
    __shared__ float sexp[4][VV];
    __shared__ float ssum[4];
    __shared__ int   stk[4];

    int tid = threadIdx.x;
    int b0 = blockIdx.x * 4;

#pragma unroll
    for (int j = 0; j < 4; j++) {
        int idx4 = tid + 256 * j;          // 0..1023 float4s
        int row = idx4 >> 8;
        int c4 = idx4 & 255;
        *(float4*)&sh[row][c4 << 2] =
            *(const float4*)&h[(size_t)(b0 + row) * HH + (c4 << 2)];
    }
    __syncthreads();

    int v = tid & 127;
    int half = tid >> 7;
    float a0 = 0.0f, a1 = 0.0f;
    const float* s0 = sh[half * 2];
    const float* s1 = sh[half * 2 + 1];
#pragma unroll 8
    for (int k = 0; k < HH; k++) {
        float w = outW[(size_t)k * VV + v];
        a0 += s0[k] * w;
        a1 += s1[k] * w;
    }
    float bv = outb[v];
    slog[half * 2][v]     = a0 + bv;
    slog[half * 2 + 1][v] = a1 + bv;
    __syncthreads();

    if (tid < 128) {                       // warps 0..3, one row each
        int rw = tid >> 5;
        int lane = tid & 31;
        float m = -3.4e38f;
        int am = VV;
#pragma unroll
        for (int i = 0; i < 4; i++) {
            int vv = lane + (i << 5);
            float x = slog[rw][vv];
            if (x > m || (x == m && vv < am)) { m = x; am = vv; }
        }
#pragma unroll
        for (int off = 16; off; off >>= 1) {
            float om = __shfl_down_sync(0xffffffffu, m, off);
            int   oa = __shfl_down_sync(0xffffffffu, am, off);
            if (om > m || (om == m && oa < am)) { m = om; am = oa; }
        }
        m  = __shfl_sync(0xffffffffu, m, 0);
        am = __shfl_sync(0xffffffffu, am, 0);
        float s = 0.0f;
#pragma unroll
        for (int i = 0; i < 4; i++) {
            int vv = lane + (i << 5);
            float e = __expf(slog[rw][vv] - m);
            sexp[rw][vv] = e;
            s += e;
        }
#pragma unroll
        for (int off = 16; off; off >>= 1) s += __shfl_xor_sync(0xffffffffu, s, off);
        if (lane == 0) {
            ssum[rw] = s;
            stk[rw]  = am;
            d_tok[b0 + rw] = am;
        }
    }
    __syncthreads();

#pragma unroll
    for (int j = 0; j < 2; j++) {
        int idx = tid + 256 * j;           // 0..511
        int rw = idx >> 7;
        int vv = idx & 127;
        dout[((size_t)(b0 + rw) * LL + t) * VV + vv] = sexp[rw][vv] / ssum[rw];
    }
    if (out_size >= BB * LL * VV + LL * BB && tid < 4) {
        dout[(size_t)BB * LL * VV + (size_t)t * BB + (b0 + tid)] = (float)stk[tid];
    }
}

// ---------------- launcher ----------------
extern "C" void kernel_launch(void* const* d_in, const int* in_sizes, int n_in,
                              void* d_out, int out_size) {
    int idx = 0;
    const int* inputs = (const int*)d_in[idx++];
    if (idx < n_in && in_sizes[idx] == 1) idx++;  // skip max_len scalar if present
    const float* enc_emb = (const float*)d_in[idx++];
    const float* enc_W   = (const float*)d_in[idx++];
    const float* enc_U   = (const float*)d_in[idx++];
    const float* enc_b   = (const float*)d_in[idx++];
    const float* dec_emb = (const float*)d_in[idx++];
    const float* dec_W   = (const float*)d_in[idx++];
    const float* dec_U   = (const float*)d_in[idx++];
    const float* dec_b   = (const float*)d_in[idx++];
    const float* out_W   = (const float*)d_in[idx++];
    const float* out_b   = (const float*)d_in[idx++];
    float* dout = (float*)d_out;

    init_kernel<<<256, 256>>>();
    table_kernel<<<128, 256>>>(enc_emb, enc_W, enc_b, 0);
    table_kernel<<<128, 256>>>(dec_emb, dec_W, dec_b, 1);

    dim3 grid(GG / BN, BB / BM);  // (32, 4)
    int par = 0;
    for (int t = 0; t < TT; t++) {
        lstm_step_kernel<<<grid, 256>>>(enc_U, 0, inputs + t, TT, 0, par);
        par ^= 1;
    }
    for (int s = 0; s < LL; s++) {
        lstm_step_kernel<<<grid, 256>>>(dec_U, 1, (const int*)0, 1, 1, par);
        par ^= 1;
        dec_out_kernel<<<64, 256>>>(out_W, out_b, dout, out_size, s, par);
    }
}